// round 7
// baseline (speedup 1.0000x reference)
#include <cuda_runtime.h>

// ============================================================================
// Linear slab model — single fused kernel.
//   z_{n+1} = a*z_n + f_n,  a = (1-dt*K1) - i*dt*fc,  f_n linear per interval.
// Interval closed form (ns steps, f = p + q*m):
//   z_m = u + v*m + a^m*w,  v = q/(1-a), u = (p-v)/(1-a), w = z_start - u
// Interval-to-interval:  z_start(s) = sum_{j<s} A^{s-1-j} S_j,  A = a^ns.
// |A|^512 < 1e-25  =>  each 512-interval chunk reconstructs its start states
// exactly (f32) from a 512-interval recomputed halo. No global scan, no
// inter-kernel deps: ONE kernel, grid-strided over chunks.
//   phase1: (u,v,S) for own + halo intervals
//   phase2: weighted halo reduction + intra-block shuffle scan -> w in smem
//   phase3: stream outputs from smem, coalesced float4 stores
// ============================================================================

#define OWN   512
#define HALO  512
#define POWC  128

__device__ __forceinline__ float2 cmul(float2 a, float2 b) {
    return make_float2(fmaf(a.x, b.x, -a.y * b.y), fmaf(a.x, b.y, a.y * b.x));
}
__device__ __forceinline__ float2 cfma2(float2 A, float2 z, float2 h) {
    return make_float2(fmaf(A.x, z.x, fmaf(-A.y, z.y, h.x)),
                       fmaf(A.x, z.y, fmaf( A.y, z.x, h.y)));
}
__device__ __forceinline__ float2 cpow(float2 a, int e) {
    float2 r = make_float2(1.0f, 0.0f);
    while (e) { if (e & 1) r = cmul(r, a); a = cmul(a, a); e >>= 1; }
    return r;
}
__device__ __forceinline__ float2 cinv(float2 a) {
    float s = 1.0f / fmaf(a.x, a.x, a.y * a.y);
    return make_float2(a.x * s, -a.y * s);
}

// (u,v,S) for interval s (global index relative to j0)
__device__ __forceinline__ void interval_op(
    int s, int j0, int nl, int ns, int m0, float e, float inv_ns,
    float2 a, float2 A, float2 inv1ma,
    const float* __restrict__ TAx, const float* __restrict__ TAy,
    float2& u, float2& v, float2& S)
{
    int j  = j0 + s;
    int i1 = min(j,     nl - 1);
    int i2 = min(j + 1, nl - 1);
    float Tx0 = __ldg(TAx + i1), Tx1 = __ldg(TAx + i2);
    float Ty0 = __ldg(TAy + i1), Ty1 = __ldg(TAy + i2);
    float2 p = make_float2(e * Tx0, e * Ty0);
    float  eq = e * inv_ns;
    float2 q = make_float2(eq * (Tx1 - Tx0), eq * (Ty1 - Ty0));
    v = cmul(q, inv1ma);
    u = cmul(make_float2(p.x - v.x, p.y - v.y), inv1ma);
    int    msta = (s == 0) ? m0 : 0;
    float2 P    = (msta == 0) ? A : cpow(a, ns - msta);
    float fns = (float)ns, fm = (float)msta;
    float2 zend = make_float2(fmaf(v.x, fns, u.x), fmaf(v.y, fns, u.y));
    float2 zsta = make_float2(fmaf(v.x, fm,  u.x), fmaf(v.y, fm,  u.y));
    float2 Ps   = cmul(P, zsta);
    S = make_float2(zend.x - Ps.x, zend.y - Ps.y);
}

__global__ __launch_bounds__(OWN, 2) void kFused(
    const float* __restrict__ pk,
    const float* __restrict__ TAx, const float* __restrict__ TAy,
    const float* __restrict__ fcp,
    const int* __restrict__ t0p, const int* __restrict__ dtp,
    int nl, int nsteps, float* __restrict__ out)
{
    __shared__ float4 suv[OWN];      // (u.x,u.y,v.x,v.y) per own interval
    __shared__ float2 sw[OWN];       // w per own interval
    __shared__ float2 sE[OWN];       // scan scratch
    __shared__ float2 spow[POWC];    // a^i
    __shared__ float2 sRed[16];      // halo-reduction partials
    __shared__ float2 sAgg[16];      // warp scan aggregates

    const int tid  = threadIdx.x;
    const int lane = tid & 31;
    const int wrp  = tid >> 5;

    // consts (every thread, parallel — no serialization)
    const int   dti = dtp[0];
    const float dtf = (float)dti;
    const float c   = 1.0f - dtf * expf(pk[1]);
    const float d   = dtf * fcp[0];
    const float e   = dtf * expf(pk[0]);
    const int   ns  = 3600 / dti;
    const float inv_ns = 1.0f / (float)ns;
    const int   it0 = t0p[0] / dti;
    const int   j0  = it0 / ns;
    const int   m0  = it0 - j0 * ns;
    const int   NI  = (m0 + nsteps + ns - 1) / ns;
    const float2 a  = make_float2(c, -d);
    const float2 inv1ma = cinv(make_float2(1.0f - c, d));
    const float2 A  = cpow(a, ns);

    for (int i = tid; i < POWC; i += OWN) spow[i] = cpow(a, i);
    // (first __syncthreads below publishes spow)

    const int nchunks = (NI + OWN - 1) / OWN;
    const unsigned fullm = 0xffffffffu;

    for (int cidx = blockIdx.x; cidx < nchunks; cidx += gridDim.x) {
        const int s0 = cidx * OWN;
        const int s  = s0 + tid;

        // ---- phase 1: own interval op (+ halo) ----
        float2 u, v, S;
        interval_op(s, j0, nl, ns, m0, e, inv_ns, a, A, inv1ma, TAx, TAy, u, v, S);
        suv[tid] = make_float4(u.x, u.y, v.x, v.y);

        float2 hterm = make_float2(0.0f, 0.0f);
        if (cidx > 0) {
            float2 uh, vh, Sh;
            interval_op(s0 - HALO + tid, j0, nl, ns, m0, e, inv_ns, a, A, inv1ma,
                        TAx, TAy, uh, vh, Sh);
            hterm = cmul(cpow(A, HALO - 1 - tid), Sh);   // weight A^(511-t)
        }
        // warp+block reduction of halo terms
#pragma unroll
        for (int off = 16; off > 0; off >>= 1) {
            hterm.x += __shfl_down_sync(fullm, hterm.x, off);
            hterm.y += __shfl_down_sync(fullm, hterm.y, off);
        }
        if (lane == 0) sRed[wrp] = hterm;
        __syncthreads();
        if (wrp == 0) {
            float2 r2 = (lane < 16) ? sRed[lane] : make_float2(0.0f, 0.0f);
#pragma unroll
            for (int off = 8; off > 0; off >>= 1) {
                r2.x += __shfl_down_sync(fullm, r2.x, off);
                r2.y += __shfl_down_sync(fullm, r2.y, off);
            }
            if (lane == 0) sRed[0] = r2;
        }

        // ---- phase 2: intra-block inclusive scan of S (multiplier A) ----
        float2 Sc = S;
        float2 M  = A;
#pragma unroll
        for (int rk = 0; rk < 5; rk++) {
            int off = 1 << rk;
            float px = __shfl_up_sync(fullm, Sc.x, off);
            float py = __shfl_up_sync(fullm, Sc.y, off);
            if (lane >= off) Sc = cfma2(M, make_float2(px, py), Sc);
            M = cmul(M, M);                     // ends as A^32
        }
        if (lane == 31) sAgg[wrp] = Sc;
        __syncthreads();
        const float2 Z = sRed[0];               // halo contribution (broadcast)
        if (wrp == 0) {
            float2 T  = (lane < 16) ? sAgg[lane] : make_float2(0.0f, 0.0f);
            float2 M2 = M;                      // A^32
#pragma unroll
            for (int rk = 0; rk < 4; rk++) {
                int off = 1 << rk;
                float px = __shfl_up_sync(fullm, T.x, off);
                float py = __shfl_up_sync(fullm, T.y, off);
                if (lane >= off) T = cfma2(M2, make_float2(px, py), T);
                M2 = cmul(M2, M2);
            }
            if (lane < 16) sAgg[lane] = T;
        }
        __syncthreads();
        float2 incl = Sc;
        if (wrp > 0) incl = cfma2(cpow(A, lane + 1), sAgg[wrp - 1], incl);
        sE[tid] = incl;
        __syncthreads();
        float2 Ex  = (tid > 0) ? sE[tid - 1] : make_float2(0.0f, 0.0f);
        float2 zst = cfma2(cpow(A, tid), Z, Ex);   // start state of own interval
        float2 w;
        if (s == 0 && m0 != 0) {
            w = make_float2(zst.x - fmaf(v.x, (float)m0, u.x),
                            zst.y - fmaf(v.y, (float)m0, u.y));
            float2 pm = (m0 < POWC) ? spow[m0] : cpow(a, m0);
            w = cmul(w, cinv(pm));
        } else {
            w = make_float2(zst.x - u.x, zst.y - u.y);
        }
        sw[tid] = w;
        __syncthreads();

        // ---- phase 3: stream outputs for this chunk ----
        int nlo = s0 * ns - m0; if (nlo < 0) nlo = 0;
        int nhi = (s0 + OWN) * ns - m0; if (nhi > nsteps) nhi = nsteps;

        const int STRIDE = OWN * 12;
        int ofs = nlo + tid * 12;
        if (ofs < nhi) {
            int itab = it0 + ofs;
            int qd   = itab / ns;
            int sl   = qd - j0 - s0;
            int r    = itab - qd * ns;
            const int dsl = STRIDE / ns, drr = STRIDE - (STRIDE / ns) * ns;
            const bool fastm = ((ns % 12) == 0) && ((m0 % 12) == 0) &&
                               ((nsteps & 3) == 0);
            if (fastm) {
                while (ofs + 12 <= nhi) {
                    float4 uvq = suv[sl];
                    float2 wq  = sw[sl];
                    float2 pw  = (ns < POWC) ? spow[r + 1] : cpow(a, r + 1);
                    float2 aw  = cmul(pw, wq);
                    float  fm  = (float)(r + 1);
                    float2 base = make_float2(fmaf(uvq.z, fm, uvq.x),
                                              fmaf(uvq.w, fm, uvq.y));
#pragma unroll
                    for (int gq = 0; gq < 3; gq++) {
                        float4 Uq, Vq;
                        Uq.x = base.x + aw.x; Vq.x = base.y + aw.y;
                        base.x += uvq.z; base.y += uvq.w; aw = cmul(aw, a);
                        Uq.y = base.x + aw.x; Vq.y = base.y + aw.y;
                        base.x += uvq.z; base.y += uvq.w; aw = cmul(aw, a);
                        Uq.z = base.x + aw.x; Vq.z = base.y + aw.y;
                        base.x += uvq.z; base.y += uvq.w; aw = cmul(aw, a);
                        Uq.w = base.x + aw.x; Vq.w = base.y + aw.y;
                        base.x += uvq.z; base.y += uvq.w; aw = cmul(aw, a);
                        int o = ofs + gq * 4;
                        *reinterpret_cast<float4*>(out + o)          = Uq;
                        *reinterpret_cast<float4*>(out + nsteps + o) = Vq;
                    }
                    ofs += STRIDE;
                    sl += dsl; r += drr; if (r >= ns) { r -= ns; sl++; }
                }
                if (ofs < nhi) {                  // tail (<12, no crossing)
                    int lim = nhi - ofs;
                    float4 uvq = suv[sl];
                    float2 wq  = sw[sl];
                    float2 pw  = (ns < POWC) ? spow[r + 1] : cpow(a, r + 1);
                    float2 aw  = cmul(pw, wq);
                    float  fm  = (float)(r + 1);
                    float2 base = make_float2(fmaf(uvq.z, fm, uvq.x),
                                              fmaf(uvq.w, fm, uvq.y));
                    for (int kk = 0; kk < lim; kk++) {
                        out[ofs + kk]          = base.x + aw.x;
                        out[nsteps + ofs + kk] = base.y + aw.y;
                        base.x += uvq.z; base.y += uvq.w; aw = cmul(aw, a);
                    }
                }
            } else {
                while (ofs < nhi) {
                    int lim = min(12, nhi - ofs);
                    int sl2 = sl, m = r + 1;
                    float4 uvq = suv[sl2];
                    float2 wq  = sw[sl2];
                    float2 pw  = (m < POWC) ? spow[m] : cpow(a, m);
                    float2 aw  = cmul(pw, wq);
                    float  fm  = (float)m;
                    float2 base = make_float2(fmaf(uvq.z, fm, uvq.x),
                                              fmaf(uvq.w, fm, uvq.y));
                    for (int kk = 0; kk < lim; kk++) {
                        float2 z = make_float2(base.x + aw.x, base.y + aw.y);
                        out[ofs + kk]          = z.x;
                        out[nsteps + ofs + kk] = z.y;
                        if (kk + 1 < lim) {
                            if (m == ns) {        // crossing: z is next start
                                sl2++;
                                uvq = suv[sl2];
                                wq  = make_float2(z.x - uvq.x, z.y - uvq.y);
                                m   = 1;
                                base = make_float2(uvq.x + uvq.z, uvq.y + uvq.w);
                                aw   = cmul(a, wq);
                            } else {
                                m++;
                                base.x += uvq.z; base.y += uvq.w;
                                aw = cmul(aw, a);
                            }
                        }
                    }
                    ofs += STRIDE;
                    sl += dsl; r += drr; if (r >= ns) { r -= ns; sl++; }
                }
            }
        }
        __syncthreads();   // protect smem before next chunk
    }
}

// ---------------- host ------------------------------------------------------
extern "C" void kernel_launch(void* const* d_in, const int* in_sizes, int n_in,
                              void* d_out, int out_size)
{
    const float* pk  = (const float*)d_in[0];
    const float* TAx = (const float*)d_in[1];
    const float* TAy = (const float*)d_in[2];
    const float* fcp = (const float*)d_in[3];
    const int*   t0p = (const int*)d_in[4];
    // d_in[5] = t1 (unused; nsteps derived from out_size)
    const int*   dtp = (const int*)d_in[6];

    const int nl     = in_sizes[1];
    const int nsteps = out_size / 2;
    float* out = (float*)d_out;

    // Grid sized for ns=60 (the production case); grid-stride keeps other dt
    // values correct (more chunks per block or early-exit blocks).
    long long NIest = (long long)nsteps / 60 + 2;
    int G = (int)((NIest + OWN - 1) / OWN) + 1;
    if (G < 2) G = 2;
    if (G > 8192) G = 8192;

    kFused<<<G, OWN>>>(pk, TAx, TAy, fcp, t0p, dtp, nl, nsteps, out);
}

// round 8
// speedup vs baseline: 1.3061x; 1.3061x over previous
#include <cuda_runtime.h>

// ============================================================================
// Linear slab model, closed-form parallel solution (z_init = 0 exploited).
//   z_{n+1} = a*z_n + f_n,  a = (1-dt*K1) - i*dt*fc,  f_n linear per interval.
// Within a forcing interval (ns steps, forcing f = p + q*m):
//   z_m = u + v*m + a^m * w,   v = q/(1-a), u = (p-v)/(1-a), w = z_0 - u
// kA: per-interval S + constant-multiplier shuffle scan
// kB: scan 256 block aggregates; build g_pow / g_Apow tables + magic divisor
// kC: materialize per-interval w (so kD is minimal)
// kD: 4 consecutive outputs/thread -> PERFECTLY COALESCED float4 warp stores
//     (lane stride 16B); ns%4==0 && it0%4==0 -> no interval crossing at all.
// ============================================================================

#define SCAN_B 1024
#define MAXI   262144
#define NBMAX  (MAXI / SCAN_B)   // 256
#define POW_N  256

__device__ float4 g_uv[MAXI];     // (u.x, u.y, v.x, v.y)
__device__ float2 g_w[MAXI];      // w per interval (anchored at local m)
__device__ float2 g_prefS[MAXI];  // block-local exclusive S prefix
__device__ float2 g_aggS[NBMAX];  // per-block aggregate
__device__ float2 g_boff[NBMAX];  // global state at start of each kA block
__device__ float2 g_pow[POW_N];   // a^m, m <= ns
__device__ float2 g_Apow[SCAN_B]; // A^k, k < 1024, A = a^ns

struct DevK {
    float c, d, e, inv_ns;
    int   ns, it0, j0, m0;
    int   NI, pad;
    unsigned long long magic;      // (1<<37)/ns + 1
};
__device__ DevK g_k;

__device__ __forceinline__ float2 cmul(float2 a, float2 b) {
    return make_float2(fmaf(a.x, b.x, -a.y * b.y), fmaf(a.x, b.y, a.y * b.x));
}
__device__ __forceinline__ float2 cfma2(float2 A, float2 z, float2 h) {
    return make_float2(fmaf(A.x, z.x, fmaf(-A.y, z.y, h.x)),
                       fmaf(A.x, z.y, fmaf( A.y, z.x, h.y)));
}
__device__ __forceinline__ float2 cpow(float2 a, int e) {
    float2 r = make_float2(1.0f, 0.0f);
    while (e) { if (e & 1) r = cmul(r, a); a = cmul(a, a); e >>= 1; }
    return r;
}
__device__ __forceinline__ float2 cinv(float2 a) {
    float s = 1.0f / fmaf(a.x, a.x, a.y * a.y);
    return make_float2(a.x * s, -a.y * s);
}

// ---------------- kA ---------------------------------------------------------
__global__ __launch_bounds__(SCAN_B) void kA(
    const float* __restrict__ pk,
    const float* __restrict__ TAx, const float* __restrict__ TAy,
    const float* __restrict__ fcp,
    const int* __restrict__ t0p, const int* __restrict__ dtp,
    int nl, int nsteps)
{
    __shared__ DevK   skk;
    __shared__ float2 sInv1ma;
    __shared__ float2 sLane[32];   // A^1 .. A^32
    __shared__ float2 sWoff[5];    // A^{32*2^k}
    __shared__ float2 wAgg[32];
    __shared__ float2 sS[SCAN_B];

    const int tid  = threadIdx.x;
    const int lane = tid & 31;
    const int wrp  = tid >> 5;

    if (tid == 0) {
        DevK dk;
        int   dti = dtp[0];
        float dtf = (float)dti;
        dk.c = 1.0f - dtf * expf(pk[1]);
        dk.d = dtf * fcp[0];
        dk.e = dtf * expf(pk[0]);
        dk.ns = 3600 / dti;
        dk.inv_ns = 1.0f / (float)dk.ns;
        dk.it0 = t0p[0] / dti;
        dk.j0 = dk.it0 / dk.ns;
        dk.m0 = dk.it0 - dk.j0 * dk.ns;
        dk.NI = (dk.m0 + nsteps + dk.ns - 1) / dk.ns;
        dk.pad = 0;
        dk.magic = (1ull << 37) / (unsigned long long)dk.ns + 1ull;
        skk = dk;
        if (blockIdx.x == 0) g_k = dk;
        sInv1ma = cinv(make_float2(1.0f - dk.c, dk.d));

        float2 a = make_float2(dk.c, -dk.d);
        float2 A = cpow(a, dk.ns);
        float2 p = A;
        sLane[0] = A;
        for (int i = 1; i < 32; i++) { p = cmul(p, A); sLane[i] = p; }
        float2 q = p;                       // A^32
        for (int i = 0; i < 5; i++) { sWoff[i] = q; q = cmul(q, q); }
    }
    __syncthreads();

    const DevK k = skk;
    const int  s = blockIdx.x * SCAN_B + tid;
    const bool valid = (s < k.NI);
    const float2 a = make_float2(k.c, -k.d);

    float2 S = make_float2(0.0f, 0.0f);
    if (valid) {
        int j  = k.j0 + s;
        int i1 = min(j,     nl - 1);
        int i2 = min(j + 1, nl - 1);
        float Tx0 = TAx[i1], Tx1 = TAx[i2];
        float Ty0 = TAy[i1], Ty1 = TAy[i2];
        float2 inv1ma = sInv1ma;
        float2 p = make_float2(k.e * Tx0, k.e * Ty0);
        float  eq = k.e * k.inv_ns;
        float2 q = make_float2(eq * (Tx1 - Tx0), eq * (Ty1 - Ty0));
        float2 v = cmul(q, inv1ma);
        float2 u = cmul(make_float2(p.x - v.x, p.y - v.y), inv1ma);
        g_uv[s] = make_float4(u.x, u.y, v.x, v.y);

        int    msta = (s == 0) ? k.m0 : 0;
        float2 P    = (msta == 0) ? sLane[0] : cpow(a, k.ns - msta);
        float fns = (float)k.ns, fm = (float)msta;
        float2 zend = make_float2(fmaf(v.x, fns, u.x), fmaf(v.y, fns, u.y));
        float2 zsta = make_float2(fmaf(v.x, fm,  u.x), fmaf(v.y, fm,  u.y));
        float2 Ps   = cmul(P, zsta);
        S = make_float2(zend.x - Ps.x, zend.y - Ps.y);
    }

    const unsigned full = 0xffffffffu;
#pragma unroll
    for (int rk = 0; rk < 5; rk++) {
        int off = 1 << rk;
        float2 M = sLane[off - 1];
        float pSx = __shfl_up_sync(full, S.x, off);
        float pSy = __shfl_up_sync(full, S.y, off);
        if (lane >= off) S = cfma2(M, make_float2(pSx, pSy), S);
    }
    if (lane == 31) wAgg[wrp] = S;
    __syncthreads();
    if (wrp == 0) {
        float2 T = wAgg[lane];
#pragma unroll
        for (int rk = 0; rk < 5; rk++) {
            int off = 1 << rk;
            float2 M = sWoff[rk];              // A^{32*off}
            float pTx = __shfl_up_sync(full, T.x, off);
            float pTy = __shfl_up_sync(full, T.y, off);
            if (lane >= off) T = cfma2(M, make_float2(pTx, pTy), T);
        }
        wAgg[lane] = T;
    }
    __syncthreads();
    if (wrp > 0)
        S = cfma2(sLane[lane], wAgg[wrp - 1], S);   // A^{lane+1}*prevwarps + S
    sS[tid] = S;
    __syncthreads();
    if (valid)
        g_prefS[s] = (tid > 0) ? sS[tid - 1] : make_float2(0.0f, 0.0f);
    if (tid == SCAN_B - 1)
        g_aggS[blockIdx.x] = S;
}

// ---------------- kB: aggregate scan + tables --------------------------------
__global__ __launch_bounds__(NBMAX) void kB(int nsteps)
{
    __shared__ float2 sBL[32];   // B^1 .. B^32
    __shared__ float2 sBW[3];
    __shared__ float2 sS[NBMAX];
    __shared__ float2 wAgg[8];

    const int tid  = threadIdx.x;
    const int lane = tid & 31;
    const int wrp  = tid >> 5;

    const DevK k = g_k;
    const float2 a = make_float2(k.c, -k.d);
    const float2 A = cpow(a, k.ns);

    for (int i = tid; i < POW_N; i += NBMAX)
        if (i <= k.ns) g_pow[i] = cpow(a, i);
    for (int i = tid; i < SCAN_B; i += NBMAX)
        g_Apow[i] = cpow(A, i);

    if (tid == 0) {
        float2 B = cpow(A, SCAN_B);
        float2 p = B;
        sBL[0] = B;
        for (int i = 1; i < 32; i++) { p = cmul(p, B); sBL[i] = p; }
        float2 q = p;
        for (int i = 0; i < 3; i++) { sBW[i] = q; q = cmul(q, q); }
    }
    __syncthreads();

    const int NB = (k.NI + SCAN_B - 1) / SCAN_B;
    float2 S = (tid < NB) ? g_aggS[tid] : make_float2(0.0f, 0.0f);

    const unsigned full = 0xffffffffu;
#pragma unroll
    for (int rk = 0; rk < 5; rk++) {
        int off = 1 << rk;
        float2 M = sBL[off - 1];
        float pSx = __shfl_up_sync(full, S.x, off);
        float pSy = __shfl_up_sync(full, S.y, off);
        if (lane >= off) S = cfma2(M, make_float2(pSx, pSy), S);
    }
    if (lane == 31) wAgg[wrp] = S;
    __syncthreads();
    if (wrp == 0 && lane < 8) {
        float2 T = wAgg[lane];
#pragma unroll
        for (int rk = 0; rk < 3; rk++) {
            int off = 1 << rk;
            float2 M = sBW[rk];
            float pTx = __shfl_up_sync(0xffu, T.x, off);
            float pTy = __shfl_up_sync(0xffu, T.y, off);
            if (lane >= off) T = cfma2(M, make_float2(pTx, pTy), T);
        }
        wAgg[lane] = T;
    }
    __syncthreads();
    if (wrp > 0)
        S = cfma2(sBL[lane], wAgg[wrp - 1], S);
    sS[tid] = S;
    __syncthreads();
    g_boff[tid] = (tid > 0) ? sS[tid - 1] : make_float2(0.0f, 0.0f);
}

// ---------------- kC: materialize per-interval w -----------------------------
__global__ __launch_bounds__(256) void kC()
{
    const DevK k = g_k;
    const int s = blockIdx.x * blockDim.x + threadIdx.x;
    if (s >= k.NI) return;

    float4 uv = __ldg(g_uv + s);
    float2 Sx = __ldg(g_prefS + s);
    float2 bo = __ldg(g_boff + (s >> 10));
    float2 Ap = __ldg(g_Apow + (s & (SCAN_B - 1)));
    float2 z0 = cfma2(Ap, bo, Sx);             // state at interval start

    float2 w;
    if (s == 0 && k.m0 != 0) {
        float2 a = make_float2(k.c, -k.d);
        w = make_float2(z0.x - fmaf(uv.z, (float)k.m0, uv.x),
                        z0.y - fmaf(uv.w, (float)k.m0, uv.y));
        float2 pm = (k.m0 < POW_N) ? __ldg(g_pow + k.m0) : cpow(a, k.m0);
        w = cmul(w, cinv(pm));
    } else {
        w = make_float2(z0.x - uv.x, z0.y - uv.y);
    }
    g_w[s] = w;
}

// ---------------- kD: 4 consecutive outputs/thread, coalesced stores ---------
__global__ __launch_bounds__(256) void kD(int nsteps, float* __restrict__ out)
{
    const DevK k = g_k;
    const float2 a = make_float2(k.c, -k.d);
    const int ns = k.ns, it0 = k.it0, j0 = k.j0;

    const int t  = blockIdx.x * blockDim.x + threadIdx.x;
    const int n0 = t * 4;
    if (n0 >= nsteps) return;

    const int it = it0 + n0;
    const int sg = (int)(((unsigned long long)(unsigned)it * k.magic) >> 37);
    const int r  = it - sg * ns;
    int sidx = sg - j0;

    float4 uv = __ldg(g_uv + sidx);
    float2 w  = __ldg(g_w  + sidx);

    const bool fast = ((ns & 3) == 0) && ((it0 & 3) == 0) && (n0 + 4 <= nsteps);
    if (fast) {
        // r % 4 == 0 and r+4 <= ns: window never crosses an interval boundary
        float2 pw = (ns < POW_N) ? __ldg(g_pow + r + 1) : cpow(a, r + 1);
        float2 aw = cmul(pw, w);
        float  fm = (float)(r + 1);
        float2 base = make_float2(fmaf(uv.z, fm, uv.x), fmaf(uv.w, fm, uv.y));

        float4 Uq, Vq;
        Uq.x = base.x + aw.x; Vq.x = base.y + aw.y;
        base.x += uv.z; base.y += uv.w; aw = cmul(aw, a);
        Uq.y = base.x + aw.x; Vq.y = base.y + aw.y;
        base.x += uv.z; base.y += uv.w; aw = cmul(aw, a);
        Uq.z = base.x + aw.x; Vq.z = base.y + aw.y;
        base.x += uv.z; base.y += uv.w; aw = cmul(aw, a);
        Uq.w = base.x + aw.x; Vq.w = base.y + aw.y;

        *reinterpret_cast<float4*>(out + n0)          = Uq;
        *reinterpret_cast<float4*>(out + nsteps + n0) = Vq;
    } else {
        // scalar fallback with crossing handling
        int m = r + 1;
        float2 pw = (m < POW_N && ns < POW_N) ? __ldg(g_pow + m) : cpow(a, m);
        float2 aw = cmul(pw, w);
        float  fm = (float)m;
        float2 base = make_float2(fmaf(uv.z, fm, uv.x), fmaf(uv.w, fm, uv.y));
        int lim = min(4, nsteps - n0);
        for (int kk = 0; kk < lim; kk++) {
            float2 z = make_float2(base.x + aw.x, base.y + aw.y);
            out[n0 + kk]          = z.x;
            out[nsteps + n0 + kk] = z.y;
            if (kk + 1 < lim) {
                if (m == ns) {                 // crossing: z is next start
                    sidx = min(sidx + 1, MAXI - 1);
                    uv = __ldg(g_uv + sidx);
                    w  = make_float2(z.x - uv.x, z.y - uv.y);
                    m  = 1;
                    base = make_float2(uv.x + uv.z, uv.y + uv.w);
                    aw   = cmul(a, w);
                } else {
                    m++;
                    base.x += uv.z; base.y += uv.w;
                    aw = cmul(aw, a);
                }
            }
        }
    }
}

// ---------------- host ------------------------------------------------------
extern "C" void kernel_launch(void* const* d_in, const int* in_sizes, int n_in,
                              void* d_out, int out_size)
{
    const float* pk  = (const float*)d_in[0];
    const float* TAx = (const float*)d_in[1];
    const float* TAy = (const float*)d_in[2];
    const float* fcp = (const float*)d_in[3];
    const int*   t0p = (const int*)d_in[4];
    // d_in[5] = t1 (unused; nsteps derived from out_size)
    const int*   dtp = (const int*)d_in[6];

    const int nl     = in_sizes[1];
    const int nsteps = out_size / 2;
    float* out = (float*)d_out;

    kA<<<NBMAX, SCAN_B>>>(pk, TAx, TAy, fcp, t0p, dtp, nl, nsteps);
    kB<<<1, NBMAX>>>(nsteps);
    kC<<<MAXI / 256, 256>>>();

    const int TB = 256;
    const int nthr = (nsteps + 3) / 4;
    const int GB = (nthr + TB - 1) / TB;
    kD<<<GB, TB>>>(nsteps, out);
}

// round 9
// speedup vs baseline: 1.5006x; 1.1489x over previous
#include <cuda_runtime.h>

// ============================================================================
// Linear slab model, closed-form parallel solution (z_init = 0 exploited).
//   z_{n+1} = a*z_n + f_n,  a = (1-dt*K1) - i*dt*fc,  f_n linear per interval.
// Interval closed form (ns steps, f = p + q*m):
//   z_m = u + v*m + a^m*w,  v = q/(1-a), u = (p-v)/(1-a), w = z_start - u
// z_start(s) = sum_{j<s} A^{s-1-j} S_j,  A = a^ns.  |A|^512 <~ 2.5e-10 =>
// each 1024-interval block reconstructs its start exactly (f32) from a
// 512-interval recomputed halo.  TWO kernels total:
//   kAF: per-interval (u,v,S), halo reduction, block scan -> g_uv, g_w
//   kD : 8 outputs/thread as two coalesced float4 windows
// ============================================================================

#define SCAN_B 1024
#define MAXI   262144
#define NBLK   (MAXI / SCAN_B)   // 256
#define POW_N  256
#define HALO   512

__device__ float4 g_uv[MAXI];    // (u.x, u.y, v.x, v.y)
__device__ float2 g_w[MAXI];     // w per interval
__device__ float2 g_pow[POW_N];  // a^m, m <= ns

struct DevK {
    float c, d, e, inv_ns;
    int   ns, it0, j0, m0;
    int   NI, pad;
    unsigned long long magic;     // (1<<37)/ns + 1
};
__device__ DevK g_k;

__device__ __forceinline__ float2 cmul(float2 a, float2 b) {
    return make_float2(fmaf(a.x, b.x, -a.y * b.y), fmaf(a.x, b.y, a.y * b.x));
}
__device__ __forceinline__ float2 cfma2(float2 A, float2 z, float2 h) {
    return make_float2(fmaf(A.x, z.x, fmaf(-A.y, z.y, h.x)),
                       fmaf(A.x, z.y, fmaf( A.y, z.x, h.y)));
}
__device__ __forceinline__ float2 cpow(float2 a, int e) {
    float2 r = make_float2(1.0f, 0.0f);
    while (e) { if (e & 1) r = cmul(r, a); a = cmul(a, a); e >>= 1; }
    return r;
}
__device__ __forceinline__ float2 cinv(float2 a) {
    float s = 1.0f / fmaf(a.x, a.x, a.y * a.y);
    return make_float2(a.x * s, -a.y * s);
}

// A^e from tables: sA32[k] = A^{32k}, sLane[i] = A^{i+1}; e in [0, 1024)
__device__ __forceinline__ float2 apow_tab(int e, const float2* sLane,
                                           const float2* sA32) {
    float2 r = sA32[e >> 5];
    int lo = e & 31;
    if (lo) r = cmul(r, sLane[lo - 1]);
    return r;
}

// (u,v,S) for interval s
__device__ __forceinline__ void interval_op(
    int s, int j0, int nl, int ns, int m0, float e, float inv_ns,
    float2 a, float2 A, float2 inv1ma,
    const float* __restrict__ TAx, const float* __restrict__ TAy,
    float2& u, float2& v, float2& S)
{
    int j  = j0 + s;
    int i1 = min(j,     nl - 1);
    int i2 = min(j + 1, nl - 1);
    float Tx0 = __ldg(TAx + i1), Tx1 = __ldg(TAx + i2);
    float Ty0 = __ldg(TAy + i1), Ty1 = __ldg(TAy + i2);
    float2 p = make_float2(e * Tx0, e * Ty0);
    float  eq = e * inv_ns;
    float2 q = make_float2(eq * (Tx1 - Tx0), eq * (Ty1 - Ty0));
    v = cmul(q, inv1ma);
    u = cmul(make_float2(p.x - v.x, p.y - v.y), inv1ma);
    int    msta = (s == 0) ? m0 : 0;
    float2 P    = (msta == 0) ? A : cpow(a, ns - msta);
    float fns = (float)ns, fm = (float)msta;
    float2 zend = make_float2(fmaf(v.x, fns, u.x), fmaf(v.y, fns, u.y));
    float2 zsta = make_float2(fmaf(v.x, fm,  u.x), fmaf(v.y, fm,  u.y));
    float2 Ps   = cmul(P, zsta);
    S = make_float2(zend.x - Ps.x, zend.y - Ps.y);
}

// ---------------- kAF: fused setup (per-interval u,v,w) ----------------------
__global__ __launch_bounds__(SCAN_B) void kAF(
    const float* __restrict__ pk,
    const float* __restrict__ TAx, const float* __restrict__ TAy,
    const float* __restrict__ fcp,
    const int* __restrict__ t0p, const int* __restrict__ dtp,
    int nl, int nsteps)
{
    __shared__ float2 sLane[32];   // A^1 .. A^32
    __shared__ float2 sA32[32];    // A^{32k}
    __shared__ float2 wAgg[32];
    __shared__ float2 sS[SCAN_B];
    __shared__ float2 sZ;          // halo total = z at block start

    const int tid  = threadIdx.x;
    const int lane = tid & 31;
    const int wrp  = tid >> 5;

    // per-thread consts (parallel, no serialization)
    const int   dti = dtp[0];
    const float dtf = (float)dti;
    const float c   = 1.0f - dtf * expf(pk[1]);
    const float d   = dtf * fcp[0];
    const float e   = dtf * expf(pk[0]);
    const int   ns  = 3600 / dti;
    const float inv_ns = 1.0f / (float)ns;
    const int   it0 = t0p[0] / dti;
    const int   j0  = it0 / ns;
    const int   m0  = it0 - j0 * ns;
    const int   NI  = (m0 + nsteps + ns - 1) / ns;
    const float2 a  = make_float2(c, -d);
    const float2 inv1ma = cinv(make_float2(1.0f - c, d));
    const float2 A  = cpow(a, ns);

    const int s0 = blockIdx.x * SCAN_B;
    if (blockIdx.x == 0) {
        if (tid == 0) {
            DevK dk;
            dk.c = c; dk.d = d; dk.e = e; dk.inv_ns = inv_ns;
            dk.ns = ns; dk.it0 = it0; dk.j0 = j0; dk.m0 = m0;
            dk.NI = NI; dk.pad = 0;
            dk.magic = (1ull << 37) / (unsigned long long)ns + 1ull;
            g_k = dk;
        }
        if (tid < POW_N && tid <= ns) g_pow[tid] = cpow(a, tid);
    }
    if (s0 >= NI) return;          // uniform early exit (before any sync)

    // tables (parallel build)
    if (tid < 32)       sLane[tid]     = cpow(A, tid + 1);
    else if (tid < 64)  sA32[tid - 32] = cpow(A, (tid - 32) * 32);

    // own interval op
    const int  s = s0 + tid;
    const bool valid = (s < NI);
    float2 u, v, S;
    interval_op(s, j0, nl, ns, m0, e, inv_ns, a, A, inv1ma, TAx, TAy, u, v, S);
    if (valid) g_uv[s] = make_float4(u.x, u.y, v.x, v.y);
    if (!valid) S = make_float2(0.0f, 0.0f);

    // halo partial (raw S only; weights need tables -> after sync)
    float2 Sh = make_float2(0.0f, 0.0f);
    const bool hash = (blockIdx.x > 0) && (tid < HALO);
    if (hash) {
        float2 uh, vh;
        interval_op(s0 - HALO + tid, j0, nl, ns, m0, e, inv_ns, a, A, inv1ma,
                    TAx, TAy, uh, vh, Sh);
    }
    __syncthreads();               // tables ready

    // weighted halo reduction -> sZ
    float2 ht = make_float2(0.0f, 0.0f);
    if (hash) ht = cmul(apow_tab(HALO - 1 - tid, sLane, sA32), Sh);
    const unsigned fullm = 0xffffffffu;
#pragma unroll
    for (int off = 16; off > 0; off >>= 1) {
        ht.x += __shfl_down_sync(fullm, ht.x, off);
        ht.y += __shfl_down_sync(fullm, ht.y, off);
    }
    if (lane == 0) wAgg[wrp] = ht;
    __syncthreads();
    if (wrp == 0) {
        float2 r2 = wAgg[lane];
#pragma unroll
        for (int off = 16; off > 0; off >>= 1) {
            r2.x += __shfl_down_sync(fullm, r2.x, off);
            r2.y += __shfl_down_sync(fullm, r2.y, off);
        }
        if (lane == 0) sZ = r2;
    }
    __syncthreads();               // sZ ready; wAgg reusable

    // inclusive scan of S with constant multiplier A
    float2 Sc = S;
#pragma unroll
    for (int rk = 0; rk < 5; rk++) {
        int off = 1 << rk;
        float2 M = sLane[off - 1];
        float px = __shfl_up_sync(fullm, Sc.x, off);
        float py = __shfl_up_sync(fullm, Sc.y, off);
        if (lane >= off) Sc = cfma2(M, make_float2(px, py), Sc);
    }
    if (lane == 31) wAgg[wrp] = Sc;
    __syncthreads();
    if (wrp == 0) {
        float2 T = wAgg[lane];
#pragma unroll
        for (int rk = 0; rk < 5; rk++) {
            int off = 1 << rk;
            float2 M = sA32[off];                   // A^{32*off}
            float px = __shfl_up_sync(fullm, T.x, off);
            float py = __shfl_up_sync(fullm, T.y, off);
            if (lane >= off) T = cfma2(M, make_float2(px, py), T);
        }
        wAgg[lane] = T;
    }
    __syncthreads();
    if (wrp > 0) Sc = cfma2(sLane[lane], wAgg[wrp - 1], Sc);
    sS[tid] = Sc;
    __syncthreads();

    if (valid) {
        float2 Ex  = (tid > 0) ? sS[tid - 1] : make_float2(0.0f, 0.0f);
        float2 Apt = apow_tab(tid, sLane, sA32);
        float2 zst = cfma2(Apt, sZ, Ex);            // state at interval start
        float2 w;
        if (s == 0 && m0 != 0) {
            w = make_float2(zst.x - fmaf(v.x, (float)m0, u.x),
                            zst.y - fmaf(v.y, (float)m0, u.y));
            w = cmul(w, cinv(cpow(a, m0)));
        } else {
            w = make_float2(zst.x - u.x, zst.y - u.y);
        }
        g_w[s] = w;
    }
}

// ---------------- kD: two coalesced 4-step windows per thread ----------------
__device__ __forceinline__ void do_window(
    int n0, int nsteps, const DevK& k, float2 a, float* __restrict__ out)
{
    const int ns = k.ns, j0 = k.j0;
    const int it = k.it0 + n0;
    const int sg = (int)(((unsigned long long)(unsigned)it * k.magic) >> 37);
    const int r  = it - sg * ns;
    int sidx = sg - j0;

    float4 uv = __ldg(g_uv + sidx);
    float2 w  = __ldg(g_w  + sidx);

    const bool fast = ((ns & 3) == 0) && ((k.it0 & 3) == 0) &&
                      ((nsteps & 3) == 0) && (n0 + 4 <= nsteps);
    if (fast) {
        // r%4==0 and r+4 <= ns: window never crosses an interval boundary
        float2 pw = (ns < POW_N) ? __ldg(g_pow + r + 1) : cpow(a, r + 1);
        float2 aw = cmul(pw, w);
        float  fm = (float)(r + 1);
        float2 base = make_float2(fmaf(uv.z, fm, uv.x), fmaf(uv.w, fm, uv.y));

        float4 Uq, Vq;
        Uq.x = base.x + aw.x; Vq.x = base.y + aw.y;
        base.x += uv.z; base.y += uv.w; aw = cmul(aw, a);
        Uq.y = base.x + aw.x; Vq.y = base.y + aw.y;
        base.x += uv.z; base.y += uv.w; aw = cmul(aw, a);
        Uq.z = base.x + aw.x; Vq.z = base.y + aw.y;
        base.x += uv.z; base.y += uv.w; aw = cmul(aw, a);
        Uq.w = base.x + aw.x; Vq.w = base.y + aw.y;

        *reinterpret_cast<float4*>(out + n0)          = Uq;
        *reinterpret_cast<float4*>(out + nsteps + n0) = Vq;
    } else {
        int m = r + 1;
        float2 pw = (m < POW_N && ns < POW_N) ? __ldg(g_pow + m) : cpow(a, m);
        float2 aw = cmul(pw, w);
        float  fm = (float)m;
        float2 base = make_float2(fmaf(uv.z, fm, uv.x), fmaf(uv.w, fm, uv.y));
        int lim = min(4, nsteps - n0);
        for (int kk = 0; kk < lim; kk++) {
            float2 z = make_float2(base.x + aw.x, base.y + aw.y);
            out[n0 + kk]          = z.x;
            out[nsteps + n0 + kk] = z.y;
            if (kk + 1 < lim) {
                if (m == ns) {                 // crossing: z is next start
                    sidx = min(sidx + 1, MAXI - 1);
                    uv = __ldg(g_uv + sidx);
                    w  = make_float2(z.x - uv.x, z.y - uv.y);
                    m  = 1;
                    base = make_float2(uv.x + uv.z, uv.y + uv.w);
                    aw   = cmul(a, w);
                } else {
                    m++;
                    base.x += uv.z; base.y += uv.w;
                    aw = cmul(aw, a);
                }
            }
        }
    }
}

__global__ __launch_bounds__(256) void kD(int nsteps, int ofs4,
                                          float* __restrict__ out)
{
    const DevK k = g_k;
    const float2 a = make_float2(k.c, -k.d);

    const int t  = blockIdx.x * blockDim.x + threadIdx.x;
    const int n0 = t * 4;
    if (n0 >= nsteps) return;

    do_window(n0, nsteps, k, a, out);
    const int n1 = n0 + ofs4;
    if (n1 < nsteps) do_window(n1, nsteps, k, a, out);
}

// ---------------- host ------------------------------------------------------
extern "C" void kernel_launch(void* const* d_in, const int* in_sizes, int n_in,
                              void* d_out, int out_size)
{
    const float* pk  = (const float*)d_in[0];
    const float* TAx = (const float*)d_in[1];
    const float* TAy = (const float*)d_in[2];
    const float* fcp = (const float*)d_in[3];
    const int*   t0p = (const int*)d_in[4];
    // d_in[5] = t1 (unused; nsteps derived from out_size)
    const int*   dtp = (const int*)d_in[6];

    const int nl     = in_sizes[1];
    const int nsteps = out_size / 2;
    float* out = (float*)d_out;

    kAF<<<NBLK, SCAN_B>>>(pk, TAx, TAy, fcp, t0p, dtp, nl, nsteps);

    const int TB   = 256;
    const int nthr = (nsteps + 7) / 8;     // 8 outputs per thread
    const int ofs4 = nthr * 4;
    const int GB   = (nthr + TB - 1) / TB;
    kD<<<GB, TB>>>(nsteps, ofs4, out);
}

// round 10
// speedup vs baseline: 1.5241x; 1.0156x over previous
#include <cuda_runtime.h>

// ============================================================================
// Linear slab model, closed-form parallel solution (z_init = 0 exploited).
//   z_{n+1} = a*z_n + f_n,  a = (1-dt*K1) - i*dt*fc,  f_n linear per interval.
// Interval closed form (ns steps, f = p + q*m):
//   z_m = u + v*m + a^m*w,  v = q/(1-a), u = (p-v)/(1-a), w = z_start - u
// z_start(s) = sum_{j<s} A^{s-1-j} S_j,  A = a^ns.  |A|^512 <~ 1e-9 =>
// each 1024-interval block reconstructs its start exactly (f32) from a
// 512-interval recomputed halo.  TWO kernels total:
//   kAF: per-interval (u,v,S), halo reduction, block scan -> g_uv, g_w
//   kD : 12 outputs/thread as three coalesced float4 windows, gather/compute
//        split for MLP, streaming stores.
// ============================================================================

#define SCAN_B 1024
#define MAXI   262144
#define NBLK   (MAXI / SCAN_B)   // 256
#define POW_N  256
#define HALO   512
#define NW     3                 // windows per kD thread

__device__ float4 g_uv[MAXI];    // (u.x, u.y, v.x, v.y)
__device__ float2 g_w[MAXI];     // w per interval
__device__ float2 g_pow[POW_N];  // a^m, m <= ns

struct DevK {
    float c, d, e, inv_ns;
    int   ns, it0, j0, m0;
    int   NI, pad;
    unsigned long long magic;     // (1<<37)/ns + 1
};
__device__ DevK g_k;

__device__ __forceinline__ float2 cmul(float2 a, float2 b) {
    return make_float2(fmaf(a.x, b.x, -a.y * b.y), fmaf(a.x, b.y, a.y * b.x));
}
__device__ __forceinline__ float2 cfma2(float2 A, float2 z, float2 h) {
    return make_float2(fmaf(A.x, z.x, fmaf(-A.y, z.y, h.x)),
                       fmaf(A.x, z.y, fmaf( A.y, z.x, h.y)));
}
__device__ __forceinline__ float2 cpow(float2 a, int e) {
    float2 r = make_float2(1.0f, 0.0f);
    while (e) { if (e & 1) r = cmul(r, a); a = cmul(a, a); e >>= 1; }
    return r;
}
__device__ __forceinline__ float2 cinv(float2 a) {
    float s = 1.0f / fmaf(a.x, a.x, a.y * a.y);
    return make_float2(a.x * s, -a.y * s);
}
__device__ __forceinline__ void stcs4(float* p, float4 v) {
    asm volatile("st.global.cs.v4.f32 [%0], {%1,%2,%3,%4};"
                 :: "l"(p), "f"(v.x), "f"(v.y), "f"(v.z), "f"(v.w) : "memory");
}

// A^e from tables: sA32[k] = A^{32k}, sLane[i] = A^{i+1}; e in [0, 1024)
__device__ __forceinline__ float2 apow_tab(int e, const float2* sLane,
                                           const float2* sA32) {
    float2 r = sA32[e >> 5];
    int lo = e & 31;
    if (lo) r = cmul(r, sLane[lo - 1]);
    return r;
}

// (u,v,S) for interval s
__device__ __forceinline__ void interval_op(
    int s, int j0, int nl, int ns, int m0, float e, float inv_ns,
    float2 a, float2 A, float2 inv1ma,
    const float* __restrict__ TAx, const float* __restrict__ TAy,
    float2& u, float2& v, float2& S)
{
    int j  = j0 + s;
    int i1 = min(j,     nl - 1);
    int i2 = min(j + 1, nl - 1);
    float Tx0 = __ldg(TAx + i1), Tx1 = __ldg(TAx + i2);
    float Ty0 = __ldg(TAy + i1), Ty1 = __ldg(TAy + i2);
    float2 p = make_float2(e * Tx0, e * Ty0);
    float  eq = e * inv_ns;
    float2 q = make_float2(eq * (Tx1 - Tx0), eq * (Ty1 - Ty0));
    v = cmul(q, inv1ma);
    u = cmul(make_float2(p.x - v.x, p.y - v.y), inv1ma);
    int    msta = (s == 0) ? m0 : 0;
    float2 P    = (msta == 0) ? A : cpow(a, ns - msta);
    float fns = (float)ns, fm = (float)msta;
    float2 zend = make_float2(fmaf(v.x, fns, u.x), fmaf(v.y, fns, u.y));
    float2 zsta = make_float2(fmaf(v.x, fm,  u.x), fmaf(v.y, fm,  u.y));
    float2 Ps   = cmul(P, zsta);
    S = make_float2(zend.x - Ps.x, zend.y - Ps.y);
}

// ---------------- kAF: fused setup (per-interval u,v,w) ----------------------
__global__ __launch_bounds__(SCAN_B) void kAF(
    const float* __restrict__ pk,
    const float* __restrict__ TAx, const float* __restrict__ TAy,
    const float* __restrict__ fcp,
    const int* __restrict__ t0p, const int* __restrict__ dtp,
    int nl, int nsteps)
{
    __shared__ float2 sLane[32];   // A^1 .. A^32
    __shared__ float2 sA32[32];    // A^{32k}
    __shared__ float2 wAgg[32];
    __shared__ float2 sS[SCAN_B];
    __shared__ float2 sZ;          // halo total = z at block start

    const int tid  = threadIdx.x;
    const int lane = tid & 31;
    const int wrp  = tid >> 5;

    const int   dti = dtp[0];
    const float dtf = (float)dti;
    const float c   = 1.0f - dtf * expf(pk[1]);
    const float d   = dtf * fcp[0];
    const float e   = dtf * expf(pk[0]);
    const int   ns  = 3600 / dti;
    const float inv_ns = 1.0f / (float)ns;
    const int   it0 = t0p[0] / dti;
    const int   j0  = it0 / ns;
    const int   m0  = it0 - j0 * ns;
    const int   NI  = (m0 + nsteps + ns - 1) / ns;
    const float2 a  = make_float2(c, -d);
    const float2 inv1ma = cinv(make_float2(1.0f - c, d));
    const float2 A  = cpow(a, ns);

    const int s0 = blockIdx.x * SCAN_B;
    if (blockIdx.x == 0) {
        if (tid == 0) {
            DevK dk;
            dk.c = c; dk.d = d; dk.e = e; dk.inv_ns = inv_ns;
            dk.ns = ns; dk.it0 = it0; dk.j0 = j0; dk.m0 = m0;
            dk.NI = NI; dk.pad = 0;
            dk.magic = (1ull << 37) / (unsigned long long)ns + 1ull;
            g_k = dk;
        }
        if (tid < POW_N && tid <= ns) g_pow[tid] = cpow(a, tid);
    }
    if (s0 >= NI) return;          // uniform early exit (before any sync)

    if (tid < 32)       sLane[tid]     = cpow(A, tid + 1);
    else if (tid < 64)  sA32[tid - 32] = cpow(A, (tid - 32) * 32);

    const int  s = s0 + tid;
    const bool valid = (s < NI);
    float2 u, v, S;
    interval_op(s, j0, nl, ns, m0, e, inv_ns, a, A, inv1ma, TAx, TAy, u, v, S);
    if (valid) g_uv[s] = make_float4(u.x, u.y, v.x, v.y);
    if (!valid) S = make_float2(0.0f, 0.0f);

    float2 Sh = make_float2(0.0f, 0.0f);
    const bool hash = (blockIdx.x > 0) && (tid < HALO);
    if (hash) {
        float2 uh, vh;
        interval_op(s0 - HALO + tid, j0, nl, ns, m0, e, inv_ns, a, A, inv1ma,
                    TAx, TAy, uh, vh, Sh);
    }
    __syncthreads();               // tables ready

    float2 ht = make_float2(0.0f, 0.0f);
    if (hash) ht = cmul(apow_tab(HALO - 1 - tid, sLane, sA32), Sh);
    const unsigned fullm = 0xffffffffu;
#pragma unroll
    for (int off = 16; off > 0; off >>= 1) {
        ht.x += __shfl_down_sync(fullm, ht.x, off);
        ht.y += __shfl_down_sync(fullm, ht.y, off);
    }
    if (lane == 0) wAgg[wrp] = ht;
    __syncthreads();
    if (wrp == 0) {
        float2 r2 = wAgg[lane];
#pragma unroll
        for (int off = 16; off > 0; off >>= 1) {
            r2.x += __shfl_down_sync(fullm, r2.x, off);
            r2.y += __shfl_down_sync(fullm, r2.y, off);
        }
        if (lane == 0) sZ = r2;
    }
    __syncthreads();               // sZ ready; wAgg reusable

    float2 Sc = S;
#pragma unroll
    for (int rk = 0; rk < 5; rk++) {
        int off = 1 << rk;
        float2 M = sLane[off - 1];
        float px = __shfl_up_sync(fullm, Sc.x, off);
        float py = __shfl_up_sync(fullm, Sc.y, off);
        if (lane >= off) Sc = cfma2(M, make_float2(px, py), Sc);
    }
    if (lane == 31) wAgg[wrp] = Sc;
    __syncthreads();
    if (wrp == 0) {
        float2 T = wAgg[lane];
#pragma unroll
        for (int rk = 0; rk < 5; rk++) {
            int off = 1 << rk;
            float2 M = sA32[off];                   // A^{32*off}
            float px = __shfl_up_sync(fullm, T.x, off);
            float py = __shfl_up_sync(fullm, T.y, off);
            if (lane >= off) T = cfma2(M, make_float2(px, py), T);
        }
        wAgg[lane] = T;
    }
    __syncthreads();
    if (wrp > 0) Sc = cfma2(sLane[lane], wAgg[wrp - 1], Sc);
    sS[tid] = Sc;
    __syncthreads();

    if (valid) {
        float2 Ex  = (tid > 0) ? sS[tid - 1] : make_float2(0.0f, 0.0f);
        float2 Apt = apow_tab(tid, sLane, sA32);
        float2 zst = cfma2(Apt, sZ, Ex);            // state at interval start
        float2 w;
        if (s == 0 && m0 != 0) {
            w = make_float2(zst.x - fmaf(v.x, (float)m0, u.x),
                            zst.y - fmaf(v.y, (float)m0, u.y));
            w = cmul(w, cinv(cpow(a, m0)));
        } else {
            w = make_float2(zst.x - u.x, zst.y - u.y);
        }
        g_w[s] = w;
    }
}

// ---------------- kD: NW coalesced 4-step windows per thread -----------------
// scalar fallback with crossing handling (edge cases only)
__device__ __noinline__ void slow_window(
    int n0, int nsteps, const DevK k, float2 a, float* __restrict__ out)
{
    const int ns = k.ns;
    const int it = k.it0 + n0;
    const int sg = (int)(((unsigned long long)(unsigned)it * k.magic) >> 37);
    int r    = it - sg * ns;
    int sidx = sg - k.j0;

    float4 uv = __ldg(g_uv + sidx);
    float2 w  = __ldg(g_w  + sidx);
    int m = r + 1;
    float2 pw = (m < POW_N && ns < POW_N) ? __ldg(g_pow + m) : cpow(a, m);
    float2 aw = cmul(pw, w);
    float  fm = (float)m;
    float2 base = make_float2(fmaf(uv.z, fm, uv.x), fmaf(uv.w, fm, uv.y));
    int lim = min(4, nsteps - n0);
    for (int kk = 0; kk < lim; kk++) {
        float2 z = make_float2(base.x + aw.x, base.y + aw.y);
        out[n0 + kk]          = z.x;
        out[nsteps + n0 + kk] = z.y;
        if (kk + 1 < lim) {
            if (m == ns) {
                sidx = min(sidx + 1, MAXI - 1);
                uv = __ldg(g_uv + sidx);
                w  = make_float2(z.x - uv.x, z.y - uv.y);
                m  = 1;
                base = make_float2(uv.x + uv.z, uv.y + uv.w);
                aw   = cmul(a, w);
            } else {
                m++;
                base.x += uv.z; base.y += uv.w;
                aw = cmul(aw, a);
            }
        }
    }
}

__global__ __launch_bounds__(256) void kD(int nsteps, int ofs4,
                                          float* __restrict__ out)
{
    const DevK k = g_k;
    const float2 a = make_float2(k.c, -k.d);
    const int ns = k.ns;

    const int t  = blockIdx.x * blockDim.x + threadIdx.x;
    const int n0 = t * 4;
    if (n0 >= nsteps) return;

    const bool allfast = ((ns & 3) == 0) && ((k.it0 & 3) == 0) &&
                         ((nsteps & 3) == 0) && (ns < POW_N);

    if (allfast) {
        // ---- gather phase: indices + loads for all windows (max MLP) ----
        int   nn[NW], rr[NW];
        bool  act[NW];
        float4 uv[NW];
        float2 wv[NW], pw[NW];
#pragma unroll
        for (int i = 0; i < NW; i++) {
            int n = n0 + i * ofs4;
            act[i] = (n + 4 <= nsteps);
            nn[i] = act[i] ? n : 0;
            int it = k.it0 + nn[i];
            int sg = (int)(((unsigned long long)(unsigned)it * k.magic) >> 37);
            rr[i] = it - sg * ns;
            int sidx = sg - k.j0;
            uv[i] = __ldg(g_uv + sidx);
            wv[i] = __ldg(g_w  + sidx);
            pw[i] = __ldg(g_pow + rr[i] + 1);
        }
        // ---- compute + store phase (r%4==0, window never crosses) ----
#pragma unroll
        for (int i = 0; i < NW; i++) {
            if (!act[i]) continue;
            float2 aw = cmul(pw[i], wv[i]);
            float  fm = (float)(rr[i] + 1);
            float2 base = make_float2(fmaf(uv[i].z, fm, uv[i].x),
                                      fmaf(uv[i].w, fm, uv[i].y));
            float4 Uq, Vq;
            Uq.x = base.x + aw.x; Vq.x = base.y + aw.y;
            base.x += uv[i].z; base.y += uv[i].w; aw = cmul(aw, a);
            Uq.y = base.x + aw.x; Vq.y = base.y + aw.y;
            base.x += uv[i].z; base.y += uv[i].w; aw = cmul(aw, a);
            Uq.z = base.x + aw.x; Vq.z = base.y + aw.y;
            base.x += uv[i].z; base.y += uv[i].w; aw = cmul(aw, a);
            Uq.w = base.x + aw.x; Vq.w = base.y + aw.y;
            stcs4(out + nn[i], Uq);
            stcs4(out + nsteps + nn[i], Vq);
        }
        // tail windows not handled by fast path
#pragma unroll
        for (int i = 0; i < NW; i++) {
            int n = n0 + i * ofs4;
            if (n < nsteps && n + 4 > nsteps)
                slow_window(n, nsteps, k, a, out);
        }
    } else {
#pragma unroll
        for (int i = 0; i < NW; i++) {
            int n = n0 + i * ofs4;
            if (n < nsteps) slow_window(n, nsteps, k, a, out);
        }
    }
}

// ---------------- host ------------------------------------------------------
extern "C" void kernel_launch(void* const* d_in, const int* in_sizes, int n_in,
                              void* d_out, int out_size)
{
    const float* pk  = (const float*)d_in[0];
    const float* TAx = (const float*)d_in[1];
    const float* TAy = (const float*)d_in[2];
    const float* fcp = (const float*)d_in[3];
    const int*   t0p = (const int*)d_in[4];
    // d_in[5] = t1 (unused; nsteps derived from out_size)
    const int*   dtp = (const int*)d_in[6];

    const int nl     = in_sizes[1];
    const int nsteps = out_size / 2;
    float* out = (float*)d_out;

    kAF<<<NBLK, SCAN_B>>>(pk, TAx, TAy, fcp, t0p, dtp, nl, nsteps);

    const int TB   = 256;
    const int nthr = (nsteps + NW * 4 - 1) / (NW * 4);   // 12 outputs/thread
    const int ofs4 = nthr * 4;
    const int GB   = (nthr + TB - 1) / TB;
    kD<<<GB, TB>>>(nsteps, ofs4, out);
}